// round 2
// baseline (speedup 1.0000x reference)
#include <cuda_runtime.h>
#include <cuda_bf16.h>
#include <stdint.h>

#define NB   512
#define NL   64
#define NH   128
#define NENT 200000
#define NREL 500

// ---------------- scratch (__device__ globals; no allocs allowed) ----------
__device__ float g_Rproj[NREL * NH];        // relation_emb @ in_W[128:256]
__device__ float g_vdW[NH];                 // delta_W @ in_W[256:384]
__device__ float g_vdb[NH];                 // delta_b @ in_W[256:384]
__device__ __nv_bfloat16 g_Ph[NB * NH];     // (q+ctx)*rel, bf16 hi
__device__ __nv_bfloat16 g_Pl[NB * NH];     // bf16 lo
__device__ __nv_bfloat16 g_Eh[(size_t)NENT * NH];  // entity_emb hi
__device__ __nv_bfloat16 g_El[(size_t)NENT * NH];  // entity_emb lo

// ---------------- convert entity table to split bf16 -----------------------
__global__ void convertE_kernel(const float* __restrict__ E) {
    int i = blockIdx.x * blockDim.x + threadIdx.x;      // one float4
    float4 v = ((const float4*)E)[i];
    __nv_bfloat16 h0 = __float2bfloat16(v.x);
    __nv_bfloat16 h1 = __float2bfloat16(v.y);
    __nv_bfloat16 h2 = __float2bfloat16(v.z);
    __nv_bfloat16 h3 = __float2bfloat16(v.w);
    __nv_bfloat16 l0 = __float2bfloat16(v.x - __bfloat162float(h0));
    __nv_bfloat16 l1 = __float2bfloat16(v.y - __bfloat162float(h1));
    __nv_bfloat16 l2 = __float2bfloat16(v.z - __bfloat162float(h2));
    __nv_bfloat16 l3 = __float2bfloat16(v.w - __bfloat162float(h3));
    ((__nv_bfloat162*)g_Eh)[2*i+0] = __halves2bfloat162(h0, h1);
    ((__nv_bfloat162*)g_Eh)[2*i+1] = __halves2bfloat162(h2, h3);
    ((__nv_bfloat162*)g_El)[2*i+0] = __halves2bfloat162(l0, l1);
    ((__nv_bfloat162*)g_El)[2*i+1] = __halves2bfloat162(l2, l3);
}

// ---------------- prep: fold relation/delta projections --------------------
__global__ void prep_kernel(const float* __restrict__ relation_emb,
                            const float* __restrict__ in_W,
                            const float* __restrict__ delta_W,
                            const float* __restrict__ delta_b) {
    int r = blockIdx.x, j = threadIdx.x;
    if (r < NREL) {
        __shared__ float sr[NH];
        sr[j] = relation_emb[r * NH + j];
        __syncthreads();
        float acc = 0.f;
        #pragma unroll 8
        for (int i = 0; i < NH; i++) acc += sr[i] * in_W[(NH + i) * NH + j];
        g_Rproj[r * NH + j] = acc;
    } else if (r == NREL) {
        float acc = 0.f;
        #pragma unroll 8
        for (int t = 0; t < 128; t++) acc += delta_W[t] * in_W[(256 + t) * NH + j];
        g_vdW[j] = acc;
    } else {
        float acc = 0.f;
        #pragma unroll 8
        for (int t = 0; t < 128; t++) acc += delta_b[t] * in_W[(256 + t) * NH + j];
        g_vdb[j] = acc;
    }
}

// ---------------- front: one CTA per batch row ------------------------------
#define FRONT_SMEM (19968 * 4)
__global__ __launch_bounds__(256) void front_kernel(
    const int* __restrict__ heads, const int* __restrict__ relations,
    const int* __restrict__ times, const int* __restrict__ hist_ent,
    const int* __restrict__ hist_rel, const float* __restrict__ hist_delta,
    const float* __restrict__ hist_mask, const float* __restrict__ entity_emb,
    const float* __restrict__ relation_emb, const float* __restrict__ time_emb,
    const float* __restrict__ query_W, const float* __restrict__ query_b,
    const float* __restrict__ in_W, const float* __restrict__ in_b,
    const float* __restrict__ a_W, const float* __restrict__ a_b,
    const float* __restrict__ hyper_in_W, const float* __restrict__ hyper_in_b,
    const float* __restrict__ hyper_gate_W, const float* __restrict__ hyper_gate_b,
    const float* __restrict__ attn_W, const float* __restrict__ attn_b)
{
    extern __shared__ float sm[];
    float* s_NE   = sm;             // 64*128 neighbor embeds (aliased as A later)
    float* s_X    = sm + 8192;      // 64*128 x -> history_seq
    float* s_W    = sm + 16384;     // 16*128 weight staging
    float* s_misc = sm + 18432;
    float* s_rel    = s_misc;            // 128
    float* s_q      = s_misc + 128;      // 128
    float* s_cgate  = s_misc + 256;      // 128
    float* s_bias   = s_misc + 384;      // 128 = in_b + cond_in + vdb
    float* s_vdW    = s_misc + 512;      // 128
    float* s_attnW  = s_misc + 640;      // 256
    float* s_head   = s_misc + 896;      // 128
    float* s_tf     = s_misc + 1024;     // 128
    float* s_scores = s_misc + 1152;     // 64
    float* s_attn   = s_misc + 1216;     // 64
    float* s_delta  = s_misc + 1280;     // 64
    float* s_mask   = s_misc + 1344;     // 64
    int*   s_hr     = (int*)(s_misc + 1408); // 64
    float* s_qdot   = s_misc + 1472;     // 1
    float* s_A = s_NE;

    int b = blockIdx.x, tid = threadIdx.x;

    // ---- phase 0 ----
    if (tid < 128) {
        s_head[tid] = entity_emb[(size_t)heads[b] * NH + tid];
        s_rel[tid]  = relation_emb[relations[b] * NH + tid];
        s_tf[tid]   = time_emb[times[b] * NH + tid];
        s_vdW[tid]  = g_vdW[tid];
    } else {
        int j = tid - 128;
        s_attnW[j]       = attn_W[j];
        s_attnW[128 + j] = attn_W[128 + j];
    }
    if (tid < 64) {
        s_delta[tid] = hist_delta[b * NL + tid];
        s_mask[tid]  = hist_mask[b * NL + tid];
        s_hr[tid]    = hist_rel[b * NL + tid];
    }
    __syncthreads();

    // ---- phase 1: q / cond ----
    if (tid < 128) {
        int j = tid;
        float acc = query_b[j];
        #pragma unroll 4
        for (int i = 0; i < 128; i++) acc += s_head[i] * query_W[i * NH + j];
        #pragma unroll 4
        for (int i = 0; i < 128; i++) acc += s_rel[i] * query_W[(128 + i) * NH + j];
        #pragma unroll 4
        for (int i = 0; i < 128; i++) acc += s_tf[i] * query_W[(256 + i) * NH + j];
        s_q[j] = acc;
    } else {
        int j = tid - 128;
        float ci = hyper_in_b[j], cg = hyper_gate_b[j];
        #pragma unroll 4
        for (int i = 0; i < 128; i++) {
            float r = s_rel[i];
            ci += r * hyper_in_W[i * NH + j];
            cg += r * hyper_gate_W[i * NH + j];
        }
        s_cgate[j] = 1.f / (1.f + expf(-cg));
        s_bias[j]  = in_b[j] + ci + g_vdb[j];
    }
    __syncthreads();

    // ---- phase 2: gather neighbor embeddings ----
    {
        int w = tid >> 5, lane = tid & 31;
        for (int l = w; l < NL; l += 8) {
            size_t e = (size_t)hist_ent[b * NL + l];
            ((float4*)(s_NE + l * NH))[lane] = ((const float4*)(entity_emb + e * NH))[lane];
        }
    }
    __syncthreads();

    int cgi = tid & 15, rgi = tid >> 4;
    int c0 = cgi * 8, r0 = rgi * 4;
    float acc[4][8];

    // ---- phase 3: X = NE @ in_W[0:128] + bias + delta*vdW + Rproj[hr] ----
    #pragma unroll
    for (int i = 0; i < 4; i++) {
        int l = r0 + i;
        float dl = s_delta[l];
        const float* rp = g_Rproj + s_hr[l] * NH + c0;
        #pragma unroll
        for (int j = 0; j < 8; j++)
            acc[i][j] = s_bias[c0 + j] + dl * s_vdW[c0 + j] + rp[j];
    }
    for (int kt = 0; kt < 8; kt++) {
        {
            int wr = tid >> 4, wc = (tid & 15) * 8;
            const float4* src = (const float4*)(in_W + (kt * 16 + wr) * NH + wc);
            float4* dst = (float4*)(s_W + wr * NH + wc);
            dst[0] = src[0]; dst[1] = src[1];
        }
        __syncthreads();
        #pragma unroll
        for (int k = 0; k < 16; k++) {
            int kk = kt * 16 + k;
            float a0 = s_NE[(r0 + 0) * NH + kk];
            float a1 = s_NE[(r0 + 1) * NH + kk];
            float a2 = s_NE[(r0 + 2) * NH + kk];
            float a3 = s_NE[(r0 + 3) * NH + kk];
            float4 b0 = *(const float4*)(s_W + k * NH + c0);
            float4 b1 = *(const float4*)(s_W + k * NH + c0 + 4);
            float bb[8] = {b0.x, b0.y, b0.z, b0.w, b1.x, b1.y, b1.z, b1.w};
            #pragma unroll
            for (int j = 0; j < 8; j++) {
                acc[0][j] += a0 * bb[j]; acc[1][j] += a1 * bb[j];
                acc[2][j] += a2 * bb[j]; acc[3][j] += a3 * bb[j];
            }
        }
        __syncthreads();
    }
    #pragma unroll
    for (int i = 0; i < 4; i++)
        #pragma unroll
        for (int j = 0; j < 8; j++)
            s_X[(r0 + i) * NH + c0 + j] = acc[i][j];
    __syncthreads();

    // ---- phase 4: A = sigmoid(X @ a_W + a_b) ----
    #pragma unroll
    for (int i = 0; i < 4; i++)
        #pragma unroll
        for (int j = 0; j < 8; j++)
            acc[i][j] = a_b[c0 + j];
    for (int kt = 0; kt < 8; kt++) {
        {
            int wr = tid >> 4, wc = (tid & 15) * 8;
            const float4* src = (const float4*)(a_W + (kt * 16 + wr) * NH + wc);
            float4* dst = (float4*)(s_W + wr * NH + wc);
            dst[0] = src[0]; dst[1] = src[1];
        }
        __syncthreads();
        #pragma unroll
        for (int k = 0; k < 16; k++) {
            int kk = kt * 16 + k;
            float a0 = s_X[(r0 + 0) * NH + kk];
            float a1 = s_X[(r0 + 1) * NH + kk];
            float a2 = s_X[(r0 + 2) * NH + kk];
            float a3 = s_X[(r0 + 3) * NH + kk];
            float4 b0 = *(const float4*)(s_W + k * NH + c0);
            float4 b1 = *(const float4*)(s_W + k * NH + c0 + 4);
            float bb[8] = {b0.x, b0.y, b0.z, b0.w, b1.x, b1.y, b1.z, b1.w};
            #pragma unroll
            for (int j = 0; j < 8; j++) {
                acc[0][j] += a0 * bb[j]; acc[1][j] += a1 * bb[j];
                acc[2][j] += a2 * bb[j]; acc[3][j] += a3 * bb[j];
            }
        }
        __syncthreads();
    }
    #pragma unroll
    for (int i = 0; i < 4; i++)
        #pragma unroll
        for (int j = 0; j < 8; j++)
            s_A[(r0 + i) * NH + c0 + j] = 1.f / (1.f + expf(-acc[i][j]));
    __syncthreads();

    // ---- phase 5: gated scan (history_seq overwrites s_X) ----
    if (tid < 128) {
        float h = 0.f, cgt = s_cgate[tid];
        for (int l = 0; l < NL; l++) {
            float x = s_X[l * NH + tid];
            float a = s_A[l * NH + tid];
            float m = s_mask[l];
            float hn = a * h + (1.f - a) * x;
            h = m * hn + (1.f - m) * h;
            s_X[l * NH + tid] = h * cgt;
        }
    }
    __syncthreads();

    // ---- phase 6: attention ----
    if (tid < 32) {
        float p = 0.f;
        for (int j = tid; j < 128; j += 32) p += s_q[j] * s_attnW[128 + j];
        #pragma unroll
        for (int o = 16; o; o >>= 1) p += __shfl_xor_sync(~0u, p, o);
        if (tid == 0) s_qdot[0] = p + attn_b[0];
    }
    __syncthreads();
    {
        int w = tid >> 5, lane = tid & 31;
        for (int l = w; l < NL; l += 8) {
            float p = 0.f;
            #pragma unroll
            for (int j = lane; j < 128; j += 32) p += s_X[l * NH + j] * s_attnW[j];
            #pragma unroll
            for (int o = 16; o; o >>= 1) p += __shfl_xor_sync(~0u, p, o);
            if (lane == 0) {
                float sc = tanhf(p + s_qdot[0]);
                s_scores[l] = (s_mask[l] <= 0.f) ? -1e9f : sc;
            }
        }
    }
    __syncthreads();
    if (tid < 32) {
        float v0 = s_scores[tid], v1 = s_scores[tid + 32];
        float mx = fmaxf(v0, v1);
        #pragma unroll
        for (int o = 16; o; o >>= 1) mx = fmaxf(mx, __shfl_xor_sync(~0u, mx, o));
        float e0 = __expf(v0 - mx) * s_mask[tid];
        float e1 = __expf(v1 - mx) * s_mask[tid + 32];
        float s = e0 + e1;
        #pragma unroll
        for (int o = 16; o; o >>= 1) s += __shfl_xor_sync(~0u, s, o);
        s = fmaxf(s, 1e-9f);
        s_attn[tid] = e0 / s;
        s_attn[tid + 32] = e1 / s;
    }
    __syncthreads();
    if (tid < 128) {
        float c = 0.f;
        #pragma unroll 4
        for (int l = 0; l < NL; l++) c += s_X[l * NH + tid] * s_attn[l];
        float P = (s_q[tid] + c) * s_rel[tid];
        __nv_bfloat16 hi = __float2bfloat16(P);
        float lo = P - __bfloat162float(hi);
        g_Ph[b * NH + tid] = hi;
        g_Pl[b * NH + tid] = __float2bfloat16(lo);
    }
}

// ---------------- score: split-bf16 MMA GEMM -------------------------------
#define SLD 72          // padded smem row stride (bf16 elems)
#define SCORE_SMEM (4 * 128 * SLD * 2)

#define MMA_BF16(d, a, b) asm volatile( \
    "mma.sync.aligned.m16n8k16.row.col.f32.bf16.bf16.f32 " \
    "{%0,%1,%2,%3},{%4,%5,%6,%7},{%8,%9},{%0,%1,%2,%3};" \
    : "+f"(d[0]), "+f"(d[1]), "+f"(d[2]), "+f"(d[3]) \
    : "r"(a[0]), "r"(a[1]), "r"(a[2]), "r"(a[3]), "r"(b[0]), "r"(b[1]))

__device__ __forceinline__ void ldfragA(uint32_t* f, const __nv_bfloat16* p) {
    f[0] = *(const uint32_t*)p;
    f[1] = *(const uint32_t*)(p + 8 * SLD);
    f[2] = *(const uint32_t*)(p + 8);
    f[3] = *(const uint32_t*)(p + 8 * SLD + 8);
}

__global__ __launch_bounds__(256) void score_kernel(float* __restrict__ out) {
    extern __shared__ __nv_bfloat16 smb[];
    __nv_bfloat16* sAh = smb;
    __nv_bfloat16* sAl = smb + 128 * SLD;
    __nv_bfloat16* sBh = smb + 2 * 128 * SLD;
    __nv_bfloat16* sBl = smb + 3 * 128 * SLD;

    int m0 = blockIdx.x * 128;          // batch tile
    int n0 = blockIdx.y * 128;          // entity tile
    int tid = threadIdx.x;
    int warp = tid >> 5, lane = tid & 31;
    int wm = (warp >> 2) * 64;          // 2 warps in m
    int wn = (warp & 3) * 32;           // 4 warps in n
    int arow = lane >> 2;
    int acol = (lane & 3) * 2;

    float acc[4][4][4];
    #pragma unroll
    for (int i = 0; i < 4; i++)
        #pragma unroll
        for (int j = 0; j < 4; j++)
            { acc[i][j][0]=0.f; acc[i][j][1]=0.f; acc[i][j][2]=0.f; acc[i][j][3]=0.f; }

    for (int kc = 0; kc < 2; kc++) {
        int k0 = kc * 64;
        __syncthreads();
        #pragma unroll
        for (int i = 0; i < 4; i++) {
            int idx = tid + i * 256;              // 0..1023
            int row = idx >> 3, c = (idx & 7) * 8;
            *(uint4*)(sAh + row * SLD + c) = *(const uint4*)(g_Ph + (size_t)(m0 + row) * NH + k0 + c);
            *(uint4*)(sAl + row * SLD + c) = *(const uint4*)(g_Pl + (size_t)(m0 + row) * NH + k0 + c);
            int er = n0 + row;
            uint4 vh = {0u,0u,0u,0u}, vl = {0u,0u,0u,0u};
            if (er < NENT) {
                vh = *(const uint4*)(g_Eh + (size_t)er * NH + k0 + c);
                vl = *(const uint4*)(g_El + (size_t)er * NH + k0 + c);
            }
            *(uint4*)(sBh + row * SLD + c) = vh;
            *(uint4*)(sBl + row * SLD + c) = vl;
        }
        __syncthreads();
        #pragma unroll
        for (int ks = 0; ks < 4; ks++) {
            int k = ks * 16;
            uint32_t aH[4][4], bH[4][2], bL[4][2];
            #pragma unroll
            for (int mt = 0; mt < 4; mt++)
                ldfragA(aH[mt], sAh + (wm + mt * 16 + arow) * SLD + k + acol);
            #pragma unroll
            for (int nt = 0; nt < 4; nt++) {
                const __nv_bfloat16* p = sBh + (wn + nt * 8 + arow) * SLD + k + acol;
                bH[nt][0] = *(const uint32_t*)p;
                bH[nt][1] = *(const uint32_t*)(p + 8);
                const __nv_bfloat16* q = sBl + (wn + nt * 8 + arow) * SLD + k + acol;
                bL[nt][0] = *(const uint32_t*)q;
                bL[nt][1] = *(const uint32_t*)(q + 8);
            }
            #pragma unroll
            for (int mt = 0; mt < 4; mt++)
                #pragma unroll
                for (int nt = 0; nt < 4; nt++) {
                    MMA_BF16(acc[mt][nt], aH[mt], bH[nt]);
                    MMA_BF16(acc[mt][nt], aH[mt], bL[nt]);
                }
            uint32_t aL[4];
            #pragma unroll
            for (int mt = 0; mt < 4; mt++) {
                ldfragA(aL, sAl + (wm + mt * 16 + arow) * SLD + k + acol);
                #pragma unroll
                for (int nt = 0; nt < 4; nt++)
                    MMA_BF16(acc[mt][nt], aL, bH[nt]);
            }
        }
    }

    // epilogue
    #pragma unroll
    for (int mt = 0; mt < 4; mt++) {
        int row = m0 + wm + mt * 16 + arow;
        #pragma unroll
        for (int nt = 0; nt < 4; nt++) {
            int col = n0 + wn + nt * 8 + acol;
            if (col < NENT) {
                *(float2*)(out + (size_t)row * NENT + col) =
                    make_float2(acc[mt][nt][0], acc[mt][nt][1]);
                *(float2*)(out + (size_t)(row + 8) * NENT + col) =
                    make_float2(acc[mt][nt][2], acc[mt][nt][3]);
            }
        }
    }
}

// ---------------- launch ----------------------------------------------------
extern "C" void kernel_launch(void* const* d_in, const int* in_sizes, int n_in,
                              void* d_out, int out_size) {
    const int*   heads        = (const int*)d_in[0];
    const int*   relations    = (const int*)d_in[1];
    const int*   times        = (const int*)d_in[2];
    const int*   hist_ent     = (const int*)d_in[3];
    const int*   hist_rel     = (const int*)d_in[4];
    const float* hist_delta   = (const float*)d_in[5];
    const float* hist_mask    = (const float*)d_in[6];
    const float* entity_emb   = (const float*)d_in[7];
    const float* relation_emb = (const float*)d_in[8];
    const float* time_emb     = (const float*)d_in[9];
    const float* delta_W      = (const float*)d_in[10];
    const float* delta_b      = (const float*)d_in[11];
    const float* query_W      = (const float*)d_in[12];
    const float* query_b      = (const float*)d_in[13];
    const float* in_W         = (const float*)d_in[14];
    const float* in_b         = (const float*)d_in[15];
    const float* a_W          = (const float*)d_in[16];
    const float* a_b          = (const float*)d_in[17];
    const float* hyper_in_W   = (const float*)d_in[18];
    const float* hyper_in_b   = (const float*)d_in[19];
    const float* hyper_gate_W = (const float*)d_in[20];
    const float* hyper_gate_b = (const float*)d_in[21];
    const float* attn_W       = (const float*)d_in[22];
    const float* attn_b       = (const float*)d_in[23];
    float* out = (float*)d_out;

    cudaFuncSetAttribute(front_kernel, cudaFuncAttributeMaxDynamicSharedMemorySize, FRONT_SMEM);
    cudaFuncSetAttribute(score_kernel, cudaFuncAttributeMaxDynamicSharedMemorySize, SCORE_SMEM);

    convertE_kernel<<<(NENT * NH / 4) / 256, 256>>>(entity_emb);
    prep_kernel<<<NREL + 2, 128>>>(relation_emb, in_W, delta_W, delta_b);
    front_kernel<<<NB, 256, FRONT_SMEM>>>(
        heads, relations, times, hist_ent, hist_rel, hist_delta, hist_mask,
        entity_emb, relation_emb, time_emb, query_W, query_b, in_W, in_b,
        a_W, a_b, hyper_in_W, hyper_in_b, hyper_gate_W, hyper_gate_b,
        attn_W, attn_b);
    score_kernel<<<dim3(4, (NENT + 127) / 128), 256, SCORE_SMEM>>>(out);
}

// round 3
// speedup vs baseline: 1.0458x; 1.0458x over previous
#include <cuda_runtime.h>
#include <cuda_bf16.h>
#include <stdint.h>

#define NB   512
#define NL   64
#define NH   128
#define NENT 200000
#define NREL 500

// ---------------- scratch (__device__ globals; no allocs allowed) ----------
__device__ float g_Rproj[NREL * NH];        // relation_emb @ in_W[128:256]
__device__ float g_vdW[NH];                 // delta_W @ in_W[256:384]
__device__ float g_vdb[NH];                 // delta_b @ in_W[256:384]
__device__ __nv_bfloat16 g_Ph[NB * NH];     // (q+ctx)*rel, bf16 hi
__device__ __nv_bfloat16 g_Pl[NB * NH];     // bf16 lo

// ---------------- prep: fold relation/delta projections --------------------
__global__ void prep_kernel(const float* __restrict__ relation_emb,
                            const float* __restrict__ in_W,
                            const float* __restrict__ delta_W,
                            const float* __restrict__ delta_b) {
    int r = blockIdx.x, j = threadIdx.x;
    if (r < NREL) {
        __shared__ float sr[NH];
        sr[j] = relation_emb[r * NH + j];
        __syncthreads();
        float acc = 0.f;
        #pragma unroll 8
        for (int i = 0; i < NH; i++) acc += sr[i] * in_W[(NH + i) * NH + j];
        g_Rproj[r * NH + j] = acc;
    } else if (r == NREL) {
        float acc = 0.f;
        #pragma unroll 8
        for (int t = 0; t < 128; t++) acc += delta_W[t] * in_W[(256 + t) * NH + j];
        g_vdW[j] = acc;
    } else {
        float acc = 0.f;
        #pragma unroll 8
        for (int t = 0; t < 128; t++) acc += delta_b[t] * in_W[(256 + t) * NH + j];
        g_vdb[j] = acc;
    }
}

// ---------------- front: one CTA per batch row ------------------------------
#define FRONT_SMEM (19968 * 4)
__global__ __launch_bounds__(256) void front_kernel(
    const int* __restrict__ heads, const int* __restrict__ relations,
    const int* __restrict__ times, const int* __restrict__ hist_ent,
    const int* __restrict__ hist_rel, const float* __restrict__ hist_delta,
    const float* __restrict__ hist_mask, const float* __restrict__ entity_emb,
    const float* __restrict__ relation_emb, const float* __restrict__ time_emb,
    const float* __restrict__ query_W, const float* __restrict__ query_b,
    const float* __restrict__ in_W, const float* __restrict__ in_b,
    const float* __restrict__ a_W, const float* __restrict__ a_b,
    const float* __restrict__ hyper_in_W, const float* __restrict__ hyper_in_b,
    const float* __restrict__ hyper_gate_W, const float* __restrict__ hyper_gate_b,
    const float* __restrict__ attn_W, const float* __restrict__ attn_b)
{
    extern __shared__ float sm[];
    float* s_NE   = sm;             // 64*128 neighbor embeds (aliased as A later)
    float* s_X    = sm + 8192;      // 64*128 x -> history_seq
    float* s_W    = sm + 16384;     // 16*128 weight staging
    float* s_misc = sm + 18432;
    float* s_rel    = s_misc;            // 128
    float* s_q      = s_misc + 128;      // 128
    float* s_cgate  = s_misc + 256;      // 128
    float* s_bias   = s_misc + 384;      // 128 = in_b + cond_in + vdb
    float* s_vdW    = s_misc + 512;      // 128
    float* s_attnW  = s_misc + 640;      // 256
    float* s_head   = s_misc + 896;      // 128
    float* s_tf     = s_misc + 1024;     // 128
    float* s_scores = s_misc + 1152;     // 64
    float* s_attn   = s_misc + 1216;     // 64
    float* s_delta  = s_misc + 1280;     // 64
    float* s_mask   = s_misc + 1344;     // 64
    int*   s_hr     = (int*)(s_misc + 1408); // 64
    float* s_qdot   = s_misc + 1472;     // 1
    float* s_A = s_NE;

    int b = blockIdx.x, tid = threadIdx.x;

    // ---- phase 0 ----
    if (tid < 128) {
        s_head[tid] = entity_emb[(size_t)heads[b] * NH + tid];
        s_rel[tid]  = relation_emb[relations[b] * NH + tid];
        s_tf[tid]   = time_emb[times[b] * NH + tid];
        s_vdW[tid]  = g_vdW[tid];
    } else {
        int j = tid - 128;
        s_attnW[j]       = attn_W[j];
        s_attnW[128 + j] = attn_W[128 + j];
    }
    if (tid < 64) {
        s_delta[tid] = hist_delta[b * NL + tid];
        s_mask[tid]  = hist_mask[b * NL + tid];
        s_hr[tid]    = hist_rel[b * NL + tid];
    }
    __syncthreads();

    // ---- phase 1: q / cond ----
    if (tid < 128) {
        int j = tid;
        float acc = query_b[j];
        #pragma unroll 4
        for (int i = 0; i < 128; i++) acc += s_head[i] * query_W[i * NH + j];
        #pragma unroll 4
        for (int i = 0; i < 128; i++) acc += s_rel[i] * query_W[(128 + i) * NH + j];
        #pragma unroll 4
        for (int i = 0; i < 128; i++) acc += s_tf[i] * query_W[(256 + i) * NH + j];
        s_q[j] = acc;
    } else {
        int j = tid - 128;
        float ci = hyper_in_b[j], cg = hyper_gate_b[j];
        #pragma unroll 4
        for (int i = 0; i < 128; i++) {
            float r = s_rel[i];
            ci += r * hyper_in_W[i * NH + j];
            cg += r * hyper_gate_W[i * NH + j];
        }
        s_cgate[j] = 1.f / (1.f + __expf(-cg));
        s_bias[j]  = in_b[j] + ci + g_vdb[j];
    }
    __syncthreads();

    // ---- phase 2: gather neighbor embeddings ----
    {
        int w = tid >> 5, lane = tid & 31;
        for (int l = w; l < NL; l += 8) {
            size_t e = (size_t)hist_ent[b * NL + l];
            ((float4*)(s_NE + l * NH))[lane] = ((const float4*)(entity_emb + e * NH))[lane];
        }
    }
    __syncthreads();

    int cgi = tid & 15, rgi = tid >> 4;
    int c0 = cgi * 8, r0 = rgi * 4;
    int wr = tid >> 4, wc = (tid & 15) * 8;   // weight-staging coords
    float acc[4][8];
    float4 pw0, pw1;                           // prefetch regs

    // ---- phase 3: X = NE @ in_W[0:128] + bias + delta*vdW + Rproj[hr] ----
    #pragma unroll
    for (int i = 0; i < 4; i++) {
        int l = r0 + i;
        float dl = s_delta[l];
        const float* rp = g_Rproj + s_hr[l] * NH + c0;
        #pragma unroll
        for (int j = 0; j < 8; j++)
            acc[i][j] = s_bias[c0 + j] + dl * s_vdW[c0 + j] + rp[j];
    }
    {
        const float4* s = (const float4*)(in_W + wr * NH + wc);
        pw0 = s[0]; pw1 = s[1];
    }
    for (int kt = 0; kt < 8; kt++) {
        __syncthreads();
        { float4* d = (float4*)(s_W + wr * NH + wc); d[0] = pw0; d[1] = pw1; }
        __syncthreads();
        if (kt < 7) {
            const float4* s = (const float4*)(in_W + ((kt + 1) * 16 + wr) * NH + wc);
            pw0 = s[0]; pw1 = s[1];
        }
        #pragma unroll
        for (int k = 0; k < 16; k++) {
            int kk = kt * 16 + k;
            float a0 = s_NE[(r0 + 0) * NH + kk];
            float a1 = s_NE[(r0 + 1) * NH + kk];
            float a2 = s_NE[(r0 + 2) * NH + kk];
            float a3 = s_NE[(r0 + 3) * NH + kk];
            float4 b0 = *(const float4*)(s_W + k * NH + c0);
            float4 b1 = *(const float4*)(s_W + k * NH + c0 + 4);
            float bb[8] = {b0.x, b0.y, b0.z, b0.w, b1.x, b1.y, b1.z, b1.w};
            #pragma unroll
            for (int j = 0; j < 8; j++) {
                acc[0][j] += a0 * bb[j]; acc[1][j] += a1 * bb[j];
                acc[2][j] += a2 * bb[j]; acc[3][j] += a3 * bb[j];
            }
        }
    }
    __syncthreads();
    #pragma unroll
    for (int i = 0; i < 4; i++)
        #pragma unroll
        for (int j = 0; j < 8; j++)
            s_X[(r0 + i) * NH + c0 + j] = acc[i][j];
    __syncthreads();

    // ---- phase 4: A = sigmoid(X @ a_W + a_b) ----
    #pragma unroll
    for (int i = 0; i < 4; i++)
        #pragma unroll
        for (int j = 0; j < 8; j++)
            acc[i][j] = a_b[c0 + j];
    {
        const float4* s = (const float4*)(a_W + wr * NH + wc);
        pw0 = s[0]; pw1 = s[1];
    }
    for (int kt = 0; kt < 8; kt++) {
        __syncthreads();
        { float4* d = (float4*)(s_W + wr * NH + wc); d[0] = pw0; d[1] = pw1; }
        __syncthreads();
        if (kt < 7) {
            const float4* s = (const float4*)(a_W + ((kt + 1) * 16 + wr) * NH + wc);
            pw0 = s[0]; pw1 = s[1];
        }
        #pragma unroll
        for (int k = 0; k < 16; k++) {
            int kk = kt * 16 + k;
            float a0 = s_X[(r0 + 0) * NH + kk];
            float a1 = s_X[(r0 + 1) * NH + kk];
            float a2 = s_X[(r0 + 2) * NH + kk];
            float a3 = s_X[(r0 + 3) * NH + kk];
            float4 b0 = *(const float4*)(s_W + k * NH + c0);
            float4 b1 = *(const float4*)(s_W + k * NH + c0 + 4);
            float bb[8] = {b0.x, b0.y, b0.z, b0.w, b1.x, b1.y, b1.z, b1.w};
            #pragma unroll
            for (int j = 0; j < 8; j++) {
                acc[0][j] += a0 * bb[j]; acc[1][j] += a1 * bb[j];
                acc[2][j] += a2 * bb[j]; acc[3][j] += a3 * bb[j];
            }
        }
    }
    __syncthreads();
    #pragma unroll
    for (int i = 0; i < 4; i++)
        #pragma unroll
        for (int j = 0; j < 8; j++)
            s_A[(r0 + i) * NH + c0 + j] = 1.f / (1.f + __expf(-acc[i][j]));
    __syncthreads();

    // ---- phase 5: gated scan (history_seq overwrites s_X) ----
    if (tid < 128) {
        float h = 0.f, cgt = s_cgate[tid];
        for (int l = 0; l < NL; l++) {
            float x = s_X[l * NH + tid];
            float a = s_A[l * NH + tid];
            float m = s_mask[l];
            float hn = a * h + (1.f - a) * x;
            h = m * hn + (1.f - m) * h;
            s_X[l * NH + tid] = h * cgt;
        }
    }
    __syncthreads();

    // ---- phase 6: attention ----
    if (tid < 32) {
        float p = 0.f;
        for (int j = tid; j < 128; j += 32) p += s_q[j] * s_attnW[128 + j];
        #pragma unroll
        for (int o = 16; o; o >>= 1) p += __shfl_xor_sync(~0u, p, o);
        if (tid == 0) s_qdot[0] = p + attn_b[0];
    }
    __syncthreads();
    {
        int w = tid >> 5, lane = tid & 31;
        for (int l = w; l < NL; l += 8) {
            float p = 0.f;
            #pragma unroll
            for (int j = lane; j < 128; j += 32) p += s_X[l * NH + j] * s_attnW[j];
            #pragma unroll
            for (int o = 16; o; o >>= 1) p += __shfl_xor_sync(~0u, p, o);
            if (lane == 0) {
                float sc = tanhf(p + s_qdot[0]);
                s_scores[l] = (s_mask[l] <= 0.f) ? -1e9f : sc;
            }
        }
    }
    __syncthreads();
    if (tid < 32) {
        float v0 = s_scores[tid], v1 = s_scores[tid + 32];
        float mx = fmaxf(v0, v1);
        #pragma unroll
        for (int o = 16; o; o >>= 1) mx = fmaxf(mx, __shfl_xor_sync(~0u, mx, o));
        float e0 = __expf(v0 - mx) * s_mask[tid];
        float e1 = __expf(v1 - mx) * s_mask[tid + 32];
        float s = e0 + e1;
        #pragma unroll
        for (int o = 16; o; o >>= 1) s += __shfl_xor_sync(~0u, s, o);
        s = fmaxf(s, 1e-9f);
        s_attn[tid] = e0 / s;
        s_attn[tid + 32] = e1 / s;
    }
    __syncthreads();
    if (tid < 128) {
        float c = 0.f;
        #pragma unroll 4
        for (int l = 0; l < NL; l++) c += s_X[l * NH + tid] * s_attn[l];
        float P = (s_q[tid] + c) * s_rel[tid];
        __nv_bfloat16 hi = __float2bfloat16(P);
        float lo = P - __bfloat162float(hi);
        g_Ph[b * NH + tid] = hi;
        g_Pl[b * NH + tid] = __float2bfloat16(lo);
    }
}

// ---------------- score: split-bf16 MMA GEMM (fp32 E loaded directly) ------
#define SLD 72          // padded smem row stride (bf16 elems); 144B, 16B-aligned
#define SCORE_SMEM (4 * 128 * SLD * 2)

#define MMA_BF16(d, a, b) asm volatile( \
    "mma.sync.aligned.m16n8k16.row.col.f32.bf16.bf16.f32 " \
    "{%0,%1,%2,%3},{%4,%5,%6,%7},{%8,%9},{%0,%1,%2,%3};" \
    : "+f"(d[0]), "+f"(d[1]), "+f"(d[2]), "+f"(d[3]) \
    : "r"(a[0]), "r"(a[1]), "r"(a[2]), "r"(a[3]), "r"(b[0]), "r"(b[1]))

#define LDSM_X4(r, addr) asm volatile( \
    "ldmatrix.sync.aligned.m8n8.x4.shared.b16 {%0,%1,%2,%3}, [%4];" \
    : "=r"((r)[0]), "=r"((r)[1]), "=r"((r)[2]), "=r"((r)[3]) : "r"(addr))

__device__ __forceinline__ uint32_t smem_u32(const void* p) {
    return (uint32_t)__cvta_generic_to_shared(p);
}

__device__ __forceinline__ void split_pack2(float x, float y,
                                            uint32_t& h, uint32_t& l) {
    __nv_bfloat16 hx = __float2bfloat16(x), hy = __float2bfloat16(y);
    __nv_bfloat16 lx = __float2bfloat16(x - __bfloat162float(hx));
    __nv_bfloat16 ly = __float2bfloat16(y - __bfloat162float(hy));
    __nv_bfloat162 hh = __halves2bfloat162(hx, hy);
    __nv_bfloat162 ll = __halves2bfloat162(lx, ly);
    h = *(uint32_t*)&hh;
    l = *(uint32_t*)&ll;
}

__global__ __launch_bounds__(256, 2) void score_kernel(
    const float* __restrict__ E, float* __restrict__ out)
{
    extern __shared__ __nv_bfloat16 smb[];
    __nv_bfloat16* sAh = smb;
    __nv_bfloat16* sAl = smb + 128 * SLD;
    __nv_bfloat16* sBh = smb + 2 * 128 * SLD;
    __nv_bfloat16* sBl = smb + 3 * 128 * SLD;

    int m0 = blockIdx.x * 128;          // batch tile (fast dim -> 4 m-CTAs share E tile in L2)
    int n0 = blockIdx.y * 128;          // entity tile
    int tid = threadIdx.x;
    int warp = tid >> 5, lane = tid & 31;
    int wm = (warp >> 2) * 64;          // 2 warps in m
    int wn = (warp & 3) * 32;           // 4 warps in n
    int arow = lane >> 2;
    int acol = (lane & 3) * 2;

    // ldmatrix lane offsets
    int aRow = lane & 15,  aCol = (lane >> 4) * 8;               // A frags
    int bRow = ((lane >> 4) << 3) + (lane & 7);                  // B frags (nt pair)
    int bCol = ((lane >> 3) & 1) * 8;

    float acc[4][4][4];
    #pragma unroll
    for (int i = 0; i < 4; i++)
        #pragma unroll
        for (int j = 0; j < 4; j++)
            { acc[i][j][0]=0.f; acc[i][j][1]=0.f; acc[i][j][2]=0.f; acc[i][j][3]=0.f; }

    for (int kc = 0; kc < 2; kc++) {
        int k0 = kc * 64;
        __syncthreads();
        #pragma unroll
        for (int i = 0; i < 4; i++) {
            int idx = tid + i * 256;              // 0..1023
            int row = idx >> 3, c = (idx & 7) * 8;
            // A: already split bf16
            *(uint4*)(sAh + row * SLD + c) = *(const uint4*)(g_Ph + (size_t)(m0 + row) * NH + k0 + c);
            *(uint4*)(sAl + row * SLD + c) = *(const uint4*)(g_Pl + (size_t)(m0 + row) * NH + k0 + c);
            // B: fp32 -> split bf16 in regs
            int er = n0 + row;
            uint4 vh = {0u,0u,0u,0u}, vl = {0u,0u,0u,0u};
            if (er < NENT) {
                const float4* ep = (const float4*)(E + (size_t)er * NH + k0 + c);
                float4 f0 = ep[0], f1 = ep[1];
                split_pack2(f0.x, f0.y, vh.x, vl.x);
                split_pack2(f0.z, f0.w, vh.y, vl.y);
                split_pack2(f1.x, f1.y, vh.z, vl.z);
                split_pack2(f1.z, f1.w, vh.w, vl.w);
            }
            *(uint4*)(sBh + row * SLD + c) = vh;
            *(uint4*)(sBl + row * SLD + c) = vl;
        }
        __syncthreads();
        #pragma unroll
        for (int ks = 0; ks < 4; ks++) {
            int k = ks * 16;
            uint32_t aH[4][4], bH[2][4], bL[2][4];
            #pragma unroll
            for (int mt = 0; mt < 4; mt++)
                LDSM_X4(aH[mt], smem_u32(sAh + (wm + mt * 16 + aRow) * SLD + k + aCol));
            #pragma unroll
            for (int p = 0; p < 2; p++) {
                LDSM_X4(bH[p], smem_u32(sBh + (wn + p * 16 + bRow) * SLD + k + bCol));
                LDSM_X4(bL[p], smem_u32(sBl + (wn + p * 16 + bRow) * SLD + k + bCol));
            }
            #pragma unroll
            for (int mt = 0; mt < 4; mt++)
                #pragma unroll
                for (int nt = 0; nt < 4; nt++) {
                    MMA_BF16(acc[mt][nt], aH[mt], (&bH[nt >> 1][(nt & 1) * 2]));
                    MMA_BF16(acc[mt][nt], aH[mt], (&bL[nt >> 1][(nt & 1) * 2]));
                }
            #pragma unroll
            for (int mt = 0; mt < 4; mt++) {
                uint32_t aL[4];
                LDSM_X4(aL, smem_u32(sAl + (wm + mt * 16 + aRow) * SLD + k + aCol));
                #pragma unroll
                for (int nt = 0; nt < 4; nt++)
                    MMA_BF16(acc[mt][nt], aL, (&bH[nt >> 1][(nt & 1) * 2]));
            }
        }
    }

    // epilogue
    #pragma unroll
    for (int mt = 0; mt < 4; mt++) {
        int row = m0 + wm + mt * 16 + arow;
        #pragma unroll
        for (int nt = 0; nt < 4; nt++) {
            int col = n0 + wn + nt * 8 + acol;
            if (col < NENT) {
                *(float2*)(out + (size_t)row * NENT + col) =
                    make_float2(acc[mt][nt][0], acc[mt][nt][1]);
                *(float2*)(out + (size_t)(row + 8) * NENT + col) =
                    make_float2(acc[mt][nt][2], acc[mt][nt][3]);
            }
        }
    }
}

// ---------------- launch ----------------------------------------------------
extern "C" void kernel_launch(void* const* d_in, const int* in_sizes, int n_in,
                              void* d_out, int out_size) {
    const int*   heads        = (const int*)d_in[0];
    const int*   relations    = (const int*)d_in[1];
    const int*   times        = (const int*)d_in[2];
    const int*   hist_ent     = (const int*)d_in[3];
    const int*   hist_rel     = (const int*)d_in[4];
    const float* hist_delta   = (const float*)d_in[5];
    const float* hist_mask    = (const float*)d_in[6];
    const float* entity_emb   = (const float*)d_in[7];
    const float* relation_emb = (const float*)d_in[8];
    const float* time_emb     = (const float*)d_in[9];
    const float* delta_W      = (const float*)d_in[10];
    const float* delta_b      = (const float*)d_in[11];
    const float* query_W      = (const float*)d_in[12];
    const float* query_b      = (const float*)d_in[13];
    const float* in_W         = (const float*)d_in[14];
    const float* in_b         = (const float*)d_in[15];
    const float* a_W          = (const float*)d_in[16];
    const float* a_b          = (const float*)d_in[17];
    const float* hyper_in_W   = (const float*)d_in[18];
    const float* hyper_in_b   = (const float*)d_in[19];
    const float* hyper_gate_W = (const float*)d_in[20];
    const float* hyper_gate_b = (const float*)d_in[21];
    const float* attn_W       = (const float*)d_in[22];
    const float* attn_b       = (const float*)d_in[23];
    float* out = (float*)d_out;

    cudaFuncSetAttribute(front_kernel, cudaFuncAttributeMaxDynamicSharedMemorySize, FRONT_SMEM);
    cudaFuncSetAttribute(score_kernel, cudaFuncAttributeMaxDynamicSharedMemorySize, SCORE_SMEM);

    prep_kernel<<<NREL + 2, 128>>>(relation_emb, in_W, delta_W, delta_b);
    front_kernel<<<NB, 256, FRONT_SMEM>>>(
        heads, relations, times, hist_ent, hist_rel, hist_delta, hist_mask,
        entity_emb, relation_emb, time_emb, query_W, query_b, in_W, in_b,
        a_W, a_b, hyper_in_W, hyper_in_b, hyper_gate_W, hyper_gate_b,
        attn_W, attn_b);
    score_kernel<<<dim3(4, (NENT + 127) / 128), 256, SCORE_SMEM>>>(entity_emb, out);
}